// round 2
// baseline (speedup 1.0000x reference)
#include <cuda_runtime.h>
#include <math.h>

#define TT 128
#define BB 32
#define VV 32000
#define EE 512
#define HH 1024
#define KK 1536          // E + H
#define GG 4096          // 4H
#define NCHUNK 250       // logits chunks of 128 vocab rows

// ---------------- scratch (no allocations allowed) ----------------
__device__ __align__(16) float g_x[EE * BB];       // x[e][b]
__device__ __align__(16) float g_h[HH * BB];       // h[k][b]
__device__ __align__(16) float g_c[HH * BB];       // c[k][b]
__device__ __align__(16) float g_gates[GG * BB];   // gates[m][b]
__device__ float2 g_part[NCHUNK * BB];             // per-chunk (max, sumexp)
__device__ float g_loss;

// ---------------- init: h0,c0 -> [k][b] layout, zero loss ----------------
__global__ void k_init(const float* __restrict__ h0, const float* __restrict__ c0) {
    int i = blockIdx.x * blockDim.x + threadIdx.x;
    if (i < HH * BB) {
        int b = i / HH, k = i % HH;
        g_h[k * BB + b] = h0[i];
        g_c[k * BB + b] = c0[i];
    }
    if (i == 0) g_loss = 0.f;
}

// ---------------- x = relu(emb[indices[t]]) into [e][b] ----------------
__global__ void k_prepx(const int* __restrict__ indices, const float* __restrict__ emb, int t) {
    int i = blockIdx.x * blockDim.x + threadIdx.x;
    if (i >= EE * BB) return;
    int b = i / EE, e = i % EE;
    int ix = indices[t * BB + b];
    float v = emb[ix * EE + e];
    g_x[e * BB + b] = fmaxf(v, 0.f);
}

// ---------------- gates GEMM: gates[4096][32] = Wcat @ xh ----------------
// M_tile=32, 256 threads, 2x2 register tile, grid = 128 blocks
__global__ void k_gates(const float* __restrict__ W_ih, const float* __restrict__ W_hh,
                        const float* __restrict__ b_ih, const float* __restrict__ b_hh) {
    __shared__ __align__(16) float As[32][36];  // [k][m]
    __shared__ __align__(16) float Bs[32][36];  // [k][b]
    int t = threadIdx.x;
    int tx = t & 15, ty = t >> 4;
    int m0 = blockIdx.x * 32;
    int lr = t >> 3;            // 0..31 (row for loads)
    int lc = (t & 7) * 4;       // 0,4,...,28 (col4 for loads)
    float acc00 = 0.f, acc01 = 0.f, acc10 = 0.f, acc11 = 0.f;

    for (int k0 = 0; k0 < KK; k0 += 32) {
        // A tile: W rows m0..m0+31, k columns k0..k0+31, stored transposed [k][m]
        float4 w;
        if (k0 < EE) w = *(const float4*)&W_ih[(m0 + lr) * EE + k0 + lc];
        else         w = *(const float4*)&W_hh[(m0 + lr) * HH + (k0 - EE) + lc];
        As[lc + 0][lr] = w.x; As[lc + 1][lr] = w.y;
        As[lc + 2][lr] = w.z; As[lc + 3][lr] = w.w;
        // B tile: xh[k0+lr][lc..lc+3]
        const float* bsrc = (k0 < EE) ? &g_x[(k0 + lr) * BB] : &g_h[(k0 - EE + lr) * BB];
        *(float4*)&Bs[lr][lc] = *(const float4*)(bsrc + lc);
        __syncthreads();
        #pragma unroll
        for (int k = 0; k < 32; k++) {
            float a0 = As[k][2 * ty], a1 = As[k][2 * ty + 1];
            float b0 = Bs[k][2 * tx], b1 = Bs[k][2 * tx + 1];
            acc00 += a0 * b0; acc01 += a0 * b1;
            acc10 += a1 * b0; acc11 += a1 * b1;
        }
        __syncthreads();
    }
    int m = m0 + 2 * ty;
    float bias0 = b_ih[m] + b_hh[m];
    float bias1 = b_ih[m + 1] + b_hh[m + 1];
    g_gates[m * BB + 2 * tx]           = acc00 + bias0;
    g_gates[m * BB + 2 * tx + 1]       = acc01 + bias0;
    g_gates[(m + 1) * BB + 2 * tx]     = acc10 + bias1;
    g_gates[(m + 1) * BB + 2 * tx + 1] = acc11 + bias1;
}

// ---------------- LSTM pointwise: update c, h ----------------
__global__ void k_lstm() {
    int i = blockIdx.x * blockDim.x + threadIdx.x;  // i = k*32 + b
    if (i >= HH * BB) return;
    int k = i >> 5, b = i & 31;
    float ig = g_gates[k * BB + b];
    float fg = g_gates[(k + HH) * BB + b];
    float gg = g_gates[(k + 2 * HH) * BB + b];
    float og = g_gates[(k + 3 * HH) * BB + b];
    float si = 1.f / (1.f + expf(-ig));
    float sf = 1.f / (1.f + expf(-fg));
    float so = 1.f / (1.f + expf(-og));
    float c = sf * g_c[i] + si * tanhf(gg);
    g_c[i] = c;
    g_h[i] = so * tanhf(c);
}

// ---------------- logits GEMM + partial logsumexp per 128-vocab chunk ----------------
// M_tile=128, 256 threads, 8x2 register tile, grid = 250 blocks
__global__ void k_logits(const float* __restrict__ W_out, const float* __restrict__ b_out) {
    __shared__ __align__(16) float As[32][136];   // [k][m], padded
    __shared__ __align__(16) float Bs[32][36];    // [k][b]
    __shared__ float redM[16][32];
    __shared__ float redS[16][32];
    int t = threadIdx.x;
    int tx = t & 15, ty = t >> 4;
    int v0 = blockIdx.x * 128;
    int lr = t >> 3;          // 0..31
    int lc = (t & 7) * 4;     // col4
    float acc[8][2];
    #pragma unroll
    for (int i = 0; i < 8; i++) { acc[i][0] = 0.f; acc[i][1] = 0.f; }

    for (int k0 = 0; k0 < HH; k0 += 32) {
        #pragma unroll
        for (int p = 0; p < 4; p++) {
            int m = p * 32 + lr;
            float4 w = *(const float4*)&W_out[(v0 + m) * HH + k0 + lc];
            As[lc + 0][m] = w.x; As[lc + 1][m] = w.y;
            As[lc + 2][m] = w.z; As[lc + 3][m] = w.w;
        }
        *(float4*)&Bs[lr][lc] = *(const float4*)&g_h[(k0 + lr) * BB + lc];
        __syncthreads();
        #pragma unroll
        for (int k = 0; k < 32; k++) {
            float a[8];
            *(float4*)&a[0] = *(const float4*)&As[k][8 * ty];
            *(float4*)&a[4] = *(const float4*)&As[k][8 * ty + 4];
            float b0 = Bs[k][2 * tx], b1 = Bs[k][2 * tx + 1];
            #pragma unroll
            for (int i = 0; i < 8; i++) {
                acc[i][0] += a[i] * b0;
                acc[i][1] += a[i] * b1;
            }
        }
        __syncthreads();
    }

    // online logsumexp over this thread's 8 vocab rows, for its 2 batches
    float mx0 = -1e30f, mx1 = -1e30f, s0 = 0.f, s1 = 0.f;
    #pragma unroll
    for (int i = 0; i < 8; i++) {
        float bo = b_out[v0 + 8 * ty + i];
        float l0 = acc[i][0] + bo;
        float l1 = acc[i][1] + bo;
        if (l0 > mx0) { s0 = s0 * expf(mx0 - l0) + 1.f; mx0 = l0; }
        else          { s0 += expf(l0 - mx0); }
        if (l1 > mx1) { s1 = s1 * expf(mx1 - l1) + 1.f; mx1 = l1; }
        else          { s1 += expf(l1 - mx1); }
    }
    redM[ty][2 * tx] = mx0;     redS[ty][2 * tx] = s0;
    redM[ty][2 * tx + 1] = mx1; redS[ty][2 * tx + 1] = s1;
    __syncthreads();
    if (t < 32) {
        float M = -1e30f, S = 0.f;
        #pragma unroll
        for (int r = 0; r < 16; r++) {
            float m2 = redM[r][t], s2 = redS[r][t];
            if (m2 > M) { S = S * expf(M - m2) + s2; M = m2; }
            else        { S += s2 * expf(m2 - M); }
        }
        g_part[blockIdx.x * BB + t] = make_float2(M, S);
    }
}

// ---------------- merge chunks, target logit, accumulate loss ----------------
__global__ void k_merge(const int* __restrict__ indices, const float* __restrict__ W_out,
                        const float* __restrict__ b_out, int t) {
    __shared__ float nll[32];
    int tid = threadIdx.x;
    int w = tid >> 5;     // warp = batch
    int l = tid & 31;
    float M = -1e30f;
    for (int c = l; c < NCHUNK; c += 32) M = fmaxf(M, g_part[c * BB + w].x);
    #pragma unroll
    for (int o = 16; o; o >>= 1) M = fmaxf(M, __shfl_xor_sync(0xFFFFFFFFu, M, o));
    float S = 0.f;
    for (int c = l; c < NCHUNK; c += 32) {
        float2 p = g_part[c * BB + w];
        S += p.y * expf(p.x - M);
    }
    #pragma unroll
    for (int o = 16; o; o >>= 1) S += __shfl_xor_sync(0xFFFFFFFFu, S, o);
    int tgt = indices[(t + 1) * BB + w];
    float z = 0.f;
    for (int e = l; e < HH; e += 32) z += g_h[e * BB + w] * W_out[tgt * HH + e];
    #pragma unroll
    for (int o = 16; o; o >>= 1) z += __shfl_xor_sync(0xFFFFFFFFu, z, o);
    if (l == 0) nll[w] = (tgt != 0) ? (logf(S) + M - (z + b_out[tgt])) : 0.f;
    __syncthreads();
    if (tid == 0) {
        float acc = g_loss;
        #pragma unroll
        for (int b = 0; b < 32; b++) acc += nll[b];
        g_loss = acc;
    }
}

__global__ void k_out(float* out, int n) {
    int i = blockIdx.x * blockDim.x + threadIdx.x;
    if (i < n) out[i] = (i == 0) ? g_loss : 0.f;
}

// ---------------- launch ----------------
extern "C" void kernel_launch(void* const* d_in, const int* in_sizes, int n_in,
                              void* d_out, int out_size) {
    const int*   indices = (const int*)d_in[0];
    const float* emb     = (const float*)d_in[1];
    const float* W_ih    = (const float*)d_in[2];
    const float* W_hh    = (const float*)d_in[3];
    const float* b_ih    = (const float*)d_in[4];
    const float* b_hh    = (const float*)d_in[5];
    const float* W_out   = (const float*)d_in[6];
    const float* b_out   = (const float*)d_in[7];
    const float* h0      = (const float*)d_in[8];
    const float* c0      = (const float*)d_in[9];

    k_init<<<(HH * BB + 255) / 256, 256>>>(h0, c0);
    for (int t = 0; t < TT - 1; t++) {
        k_prepx<<<(EE * BB + 255) / 256, 256>>>(indices, emb, t);
        k_gates<<<GG / 32, 256>>>(W_ih, W_hh, b_ih, b_hh);
        k_lstm<<<(HH * BB) / 256, 256>>>();
        k_logits<<<NCHUNK, 256>>>(W_out, b_out);
        k_merge<<<1, 1024>>>(indices, W_out, b_out, t);
    }
    k_out<<<(out_size + 255) / 256, 256>>>((float*)d_out, out_size);
}

// round 5
// speedup vs baseline: 1.8921x; 1.8921x over previous
#include <cuda_runtime.h>
#include <cuda_bf16.h>
#include <stdint.h>
#include <stddef.h>
#include <math.h>

#define TT 128
#define BB 32
#define VV 32000
#define EE 512
#define HH 1024
#define KK 1536          // E + H
#define GG 4096          // 4H
#define NCHUNK 250       // logits chunks of 128 vocab rows

// ---------------- scratch (no allocations allowed) ----------------
__device__ __align__(16) float g_x[EE * BB];       // x[e][b]
__device__ __align__(16) float g_h[HH * BB];       // h[k][b]  (fp32, for merge dot)
__device__ __align__(16) float g_c[HH * BB];       // c[k][b]
__device__ __align__(16) float g_gates[GG * BB];   // gates[m][b]
__device__ __align__(16) __nv_bfloat16 g_hb[BB * HH];   // h bf16, [b][k] K-major
__device__ __align__(16) __nv_bfloat16 g_wout[(size_t)VV * HH]; // W_out bf16 (64MB)
__device__ float2 g_part[NCHUNK * BB];             // per-chunk (max, sumexp)
__device__ float g_loss;

// ---------------- helpers ----------------
__device__ __forceinline__ uint32_t su32(const void* p) {
    uint32_t a;
    asm("{ .reg .u64 t; cvta.to.shared.u64 t, %1; cvt.u32.u64 %0, t; }" : "=r"(a) : "l"(p));
    return a;
}
#define SWZ(o) ((o) ^ (((o) >> 3) & 0x70))

__device__ __forceinline__ void ldm_x4(uint32_t* r, uint32_t addr) {
    asm volatile("ldmatrix.sync.aligned.m8n8.x4.shared.b16 {%0,%1,%2,%3}, [%4];"
                 : "=r"(r[0]), "=r"(r[1]), "=r"(r[2]), "=r"(r[3]) : "r"(addr));
}
__device__ __forceinline__ void mma16816(float* c, const uint32_t* a, const uint32_t* b) {
    asm volatile("mma.sync.aligned.m16n8k16.row.col.f32.bf16.bf16.f32 "
                 "{%0,%1,%2,%3}, {%4,%5,%6,%7}, {%8,%9}, {%0,%1,%2,%3};"
                 : "+f"(c[0]), "+f"(c[1]), "+f"(c[2]), "+f"(c[3])
                 : "r"(a[0]), "r"(a[1]), "r"(a[2]), "r"(a[3]), "r"(b[0]), "r"(b[1]));
}

// ---------------- one-time: W_out -> bf16 ----------------
__global__ void k_convert(const float* __restrict__ W) {
    size_t i = ((size_t)blockIdx.x * blockDim.x + threadIdx.x) * 4;
    float4 v = *(const float4*)(W + i);
    g_wout[i + 0] = __float2bfloat16(v.x);
    g_wout[i + 1] = __float2bfloat16(v.y);
    g_wout[i + 2] = __float2bfloat16(v.z);
    g_wout[i + 3] = __float2bfloat16(v.w);
}

// ---------------- init ----------------
__global__ void k_init(const float* __restrict__ h0, const float* __restrict__ c0) {
    int i = blockIdx.x * blockDim.x + threadIdx.x;
    if (i < HH * BB) {
        int b = i / HH, k = i % HH;
        g_h[k * BB + b] = h0[i];
        g_c[k * BB + b] = c0[i];
        g_hb[i] = __float2bfloat16(h0[i]);   // [b][k]
    }
    if (i == 0) g_loss = 0.f;
}

// ---------------- x = relu(emb[indices[t]]) into [e][b] ----------------
__global__ void k_prepx(const int* __restrict__ indices, const float* __restrict__ emb, int t) {
    int i = blockIdx.x * blockDim.x + threadIdx.x;
    if (i >= EE * BB) return;
    int b = i / EE, e = i % EE;
    int ix = indices[t * BB + b];
    float v = emb[ix * EE + e];
    g_x[e * BB + b] = fmaxf(v, 0.f);
}

// ---------------- gates GEMM (fp32 SIMT, unchanged) ----------------
__global__ void k_gates(const float* __restrict__ W_ih, const float* __restrict__ W_hh,
                        const float* __restrict__ b_ih, const float* __restrict__ b_hh) {
    __shared__ __align__(16) float As[32][36];
    __shared__ __align__(16) float Bs[32][36];
    int t = threadIdx.x;
    int tx = t & 15, ty = t >> 4;
    int m0 = blockIdx.x * 32;
    int lr = t >> 3;
    int lc = (t & 7) * 4;
    float acc00 = 0.f, acc01 = 0.f, acc10 = 0.f, acc11 = 0.f;

    for (int k0 = 0; k0 < KK; k0 += 32) {
        float4 w;
        if (k0 < EE) w = *(const float4*)&W_ih[(m0 + lr) * EE + k0 + lc];
        else         w = *(const float4*)&W_hh[(m0 + lr) * HH + (k0 - EE) + lc];
        As[lc + 0][lr] = w.x; As[lc + 1][lr] = w.y;
        As[lc + 2][lr] = w.z; As[lc + 3][lr] = w.w;
        const float* bsrc = (k0 < EE) ? &g_x[(k0 + lr) * BB] : &g_h[(k0 - EE + lr) * BB];
        *(float4*)&Bs[lr][lc] = *(const float4*)(bsrc + lc);
        __syncthreads();
        #pragma unroll
        for (int k = 0; k < 32; k++) {
            float a0 = As[k][2 * ty], a1 = As[k][2 * ty + 1];
            float b0 = Bs[k][2 * tx], b1 = Bs[k][2 * tx + 1];
            acc00 += a0 * b0; acc01 += a0 * b1;
            acc10 += a1 * b0; acc11 += a1 * b1;
        }
        __syncthreads();
    }
    int m = m0 + 2 * ty;
    float bias0 = b_ih[m] + b_hh[m];
    float bias1 = b_ih[m + 1] + b_hh[m + 1];
    g_gates[m * BB + 2 * tx]           = acc00 + bias0;
    g_gates[m * BB + 2 * tx + 1]       = acc01 + bias0;
    g_gates[(m + 1) * BB + 2 * tx]     = acc10 + bias1;
    g_gates[(m + 1) * BB + 2 * tx + 1] = acc11 + bias1;
}

// ---------------- LSTM pointwise ----------------
__global__ void k_lstm() {
    int i = blockIdx.x * blockDim.x + threadIdx.x;  // i = k*32 + b
    if (i >= HH * BB) return;
    int k = i >> 5, b = i & 31;
    float ig = g_gates[k * BB + b];
    float fg = g_gates[(k + HH) * BB + b];
    float gg = g_gates[(k + 2 * HH) * BB + b];
    float og = g_gates[(k + 3 * HH) * BB + b];
    float si = 1.f / (1.f + expf(-ig));
    float sf = 1.f / (1.f + expf(-fg));
    float so = 1.f / (1.f + expf(-og));
    float c = sf * g_c[i] + si * tanhf(gg);
    g_c[i] = c;
    float h = so * tanhf(c);
    g_h[i] = h;
    g_hb[b * HH + k] = __float2bfloat16(h);
}

// ---------------- logits via mma.sync bf16 HMMA ----------------
// 250 CTAs x 256 thr (8 warps). Warp w: vocab rows [w*16, w*16+16), all 32 batches.
// K=1024 in 16 chunks of 64; A(128x64bf16) + B(32x64bf16) staged in SW128 smem.
__global__ void k_logits_hmma(const float* __restrict__ b_out) {
    __shared__ alignas(1024) char sbuf[16384 + 4096];  // A tile | B tile (reused as logits)
    __shared__ float redM[4][32], redS[4][32];

    const int t = threadIdx.x;
    const int w = t >> 5, lane = t & 31;
    const int v0 = blockIdx.x * 128;
    const uint32_t sbA = su32(sbuf);
    const uint32_t sbB = sbA + 16384u;

    const char* wbase = (const char*)(g_wout + (size_t)v0 * HH);
    const char* hbase = (const char*)g_hb;

    // per-thread staging slots: A: 4 float4 (row=j/8, c=j%8), B: 1 float4
    const int arow[4] = { (t + 0) >> 3, (t + 256) >> 3, (t + 512) >> 3, (t + 768) >> 3 };
    const int ac = t & 7;
    const int brow = t >> 3, bc = t & 7;

    float c[16];
    #pragma unroll
    for (int i = 0; i < 16; i++) c[i] = 0.f;

    // prefetch chunk 0
    float4 ra[4], rb;
    #pragma unroll
    for (int i = 0; i < 4; i++)
        ra[i] = *(const float4*)(wbase + ((size_t)arow[i] * HH + ac * 8) * 2);
    rb = *(const float4*)(hbase + ((size_t)brow * HH + bc * 8) * 2);

    const int lr = lane & 15, lcs = (lane >> 4) << 3;       // A ldmatrix row/col
    const int bn = (lane & 7) + ((lane >> 4) << 3);         // B ldmatrix n row
    const int bko = ((lane >> 3) & 1) << 3;                 // B ldmatrix k offset

    for (int ch = 0; ch < 16; ch++) {
        __syncthreads();   // previous compute done reading smem
        #pragma unroll
        for (int i = 0; i < 4; i++)
            *(float4*)(sbuf + SWZ(arow[i] * 128 + ac * 16)) = ra[i];
        *(float4*)(sbuf + 16384 + SWZ(brow * 128 + bc * 16)) = rb;
        __syncthreads();

        if (ch < 15) {   // prefetch next chunk
            int ko = (ch + 1) * 64;
            #pragma unroll
            for (int i = 0; i < 4; i++)
                ra[i] = *(const float4*)(wbase + ((size_t)arow[i] * HH + ko + ac * 8) * 2);
            rb = *(const float4*)(hbase + ((size_t)brow * HH + ko + bc * 8) * 2);
        }

        #pragma unroll
        for (int s = 0; s < 4; s++) {
            uint32_t a[4], b01[4], b23[4];
            ldm_x4(a,   sbA + SWZ((w * 16 + lr) * 128 + (s * 16 + lcs) * 2));
            ldm_x4(b01, sbB + SWZ(bn * 128 + (s * 16 + bko) * 2));
            ldm_x4(b23, sbB + SWZ((bn + 16) * 128 + (s * 16 + bko) * 2));
            mma16816(c + 0,  a, b01 + 0);   // batch cols 0-7
            mma16816(c + 4,  a, b01 + 2);   // cols 8-15
            mma16816(c + 8,  a, b23 + 0);   // cols 16-23
            mma16816(c + 12, a, b23 + 2);   // cols 24-31
        }
    }
    __syncthreads();   // done reading smem; reuse as logits buffer

    // epilogue: spill fragments + bias to smem logits [128][33]
    float* sl = (float*)sbuf;
    {
        int r0 = w * 16 + (lane >> 2);
        float bias0 = b_out[v0 + r0];
        float bias1 = b_out[v0 + r0 + 8];
        #pragma unroll
        for (int g = 0; g < 4; g++) {
            int col = g * 8 + 2 * (lane & 3);
            sl[r0 * 33 + col]           = c[g * 4 + 0] + bias0;
            sl[r0 * 33 + col + 1]       = c[g * 4 + 1] + bias0;
            sl[(r0 + 8) * 33 + col]     = c[g * 4 + 2] + bias1;
            sl[(r0 + 8) * 33 + col + 1] = c[g * 4 + 3] + bias1;
        }
    }
    __syncthreads();

    // per-batch online logsumexp over 128 vocab rows
    if (t < 128) {
        int q = t >> 5, b = t & 31;
        float M = -1e30f, S = 0.f;
        #pragma unroll
        for (int r = 0; r < 32; r++) {
            float l = sl[(q * 32 + r) * 33 + b];
            if (l > M) { S = S * expf(M - l) + 1.f; M = l; }
            else       { S += expf(l - M); }
        }
        redM[q][b] = M; redS[q][b] = S;
    }
    __syncthreads();
    if (t < 32) {
        float M = -1e30f, S = 0.f;
        #pragma unroll
        for (int q = 0; q < 4; q++) {
            float m2 = redM[q][t], s2 = redS[q][t];
            if (m2 > M) { S = S * expf(M - m2) + s2; M = m2; }
            else        { S += s2 * expf(m2 - M); }
        }
        g_part[blockIdx.x * BB + t] = make_float2(M, S);
    }
}

// ---------------- merge chunks, target logit, accumulate loss ----------------
__global__ void k_merge(const int* __restrict__ indices, const float* __restrict__ W_out,
                        const float* __restrict__ b_out, int t) {
    __shared__ float nll[32];
    int tid = threadIdx.x;
    int w = tid >> 5;
    int l = tid & 31;
    float M = -1e30f;
    for (int c = l; c < NCHUNK; c += 32) M = fmaxf(M, g_part[c * BB + w].x);
    #pragma unroll
    for (int o = 16; o; o >>= 1) M = fmaxf(M, __shfl_xor_sync(0xFFFFFFFFu, M, o));
    float S = 0.f;
    for (int c = l; c < NCHUNK; c += 32) {
        float2 p = g_part[c * BB + w];
        S += p.y * expf(p.x - M);
    }
    #pragma unroll
    for (int o = 16; o; o >>= 1) S += __shfl_xor_sync(0xFFFFFFFFu, S, o);
    int tgt = indices[(t + 1) * BB + w];
    float z = 0.f;
    for (int e = l; e < HH; e += 32) z += g_h[e * BB + w] * W_out[tgt * HH + e];
    #pragma unroll
    for (int o = 16; o; o >>= 1) z += __shfl_xor_sync(0xFFFFFFFFu, z, o);
    if (l == 0) nll[w] = (tgt != 0) ? (logf(S) + M - (z + b_out[tgt])) : 0.f;
    __syncthreads();
    if (tid == 0) {
        float acc = g_loss;
        #pragma unroll
        for (int b = 0; b < 32; b++) acc += nll[b];
        g_loss = acc;
    }
}

__global__ void k_out(float* out, int n) {
    int i = blockIdx.x * blockDim.x + threadIdx.x;
    if (i < n) out[i] = (i == 0) ? g_loss : 0.f;
}

// ---------------- launch ----------------
extern "C" void kernel_launch(void* const* d_in, const int* in_sizes, int n_in,
                              void* d_out, int out_size) {
    const int*   indices = (const int*)d_in[0];
    const float* emb     = (const float*)d_in[1];
    const float* W_ih    = (const float*)d_in[2];
    const float* W_hh    = (const float*)d_in[3];
    const float* b_ih    = (const float*)d_in[4];
    const float* b_hh    = (const float*)d_in[5];
    const float* W_out   = (const float*)d_in[6];
    const float* b_out   = (const float*)d_in[7];
    const float* h0      = (const float*)d_in[8];
    const float* c0      = (const float*)d_in[9];

    k_convert<<<(VV * HH / 4) / 256, 256>>>(W_out);
    k_init<<<(HH * BB + 255) / 256, 256>>>(h0, c0);
    for (int t = 0; t < TT - 1; t++) {
        k_prepx<<<(EE * BB + 255) / 256, 256>>>(indices, emb, t);
        k_gates<<<GG / 32, 256>>>(W_ih, W_hh, b_ih, b_hh);
        k_lstm<<<(HH * BB) / 256, 256>>>();
        k_logits_hmma<<<NCHUNK, 256>>>(b_out);
        k_merge<<<1, 1024>>>(indices, W_out, b_out, t);
    }
    k_out<<<(out_size + 255) / 256, 256>>>((float*)d_out, out_size);
}

// round 6
// speedup vs baseline: 3.1377x; 1.6584x over previous
#include <cuda_runtime.h>
#include <cuda_bf16.h>
#include <stdint.h>
#include <stddef.h>
#include <math.h>

#define TT 128
#define BB 32
#define VV 32000
#define EE 512
#define HH 1024
#define KK 1536          // E + H
#define GG 4096          // 4H
#define NCHUNK 250       // logits chunks of 128 vocab rows

// ---------------- scratch (no allocations allowed) ----------------
__device__ __align__(16) float g_h[HH * BB];       // h[k][b]  (fp32, for merge dot)
__device__ __align__(16) float g_c[HH * BB];       // c[k][b]
__device__ __align__(16) __nv_bfloat16 g_hb[BB * HH];   // h bf16, [b][k] K-major
__device__ __align__(16) __nv_bfloat16 g_wout[(size_t)VV * HH]; // W_out bf16 (64MB)
__device__ __align__(16) __nv_bfloat16 g_wperm[(size_t)GG * KK]; // permuted W_ih|W_hh bf16 (12.6MB)
__device__ __align__(16) float g_biasp[GG];        // permuted b_ih+b_hh
__device__ float2 g_part[NCHUNK * BB];             // per-chunk (max, sumexp)
__device__ float g_loss;

// ---------------- helpers ----------------
__device__ __forceinline__ uint32_t su32(const void* p) {
    uint32_t a;
    asm("{ .reg .u64 t; cvta.to.shared.u64 t, %1; cvt.u32.u64 %0, t; }" : "=r"(a) : "l"(p));
    return a;
}
#define SWZ(o) ((o) ^ (((o) >> 3) & 0x70))

__device__ __forceinline__ void ldm_x4(uint32_t* r, uint32_t addr) {
    asm volatile("ldmatrix.sync.aligned.m8n8.x4.shared.b16 {%0,%1,%2,%3}, [%4];"
                 : "=r"(r[0]), "=r"(r[1]), "=r"(r[2]), "=r"(r[3]) : "r"(addr));
}
__device__ __forceinline__ void mma16816(float* c, const uint32_t* a, const uint32_t* b) {
    asm volatile("mma.sync.aligned.m16n8k16.row.col.f32.bf16.bf16.f32 "
                 "{%0,%1,%2,%3}, {%4,%5,%6,%7}, {%8,%9}, {%0,%1,%2,%3};"
                 : "+f"(c[0]), "+f"(c[1]), "+f"(c[2]), "+f"(c[3])
                 : "r"(a[0]), "r"(a[1]), "r"(a[2]), "r"(a[3]), "r"(b[0]), "r"(b[1]));
}
__device__ __forceinline__ uint32_t pack2(float a, float b) {
    __nv_bfloat162 p = __floats2bfloat162_rn(a, b);
    return *reinterpret_cast<uint32_t*>(&p);
}

// ---------------- one-time conversions ----------------
__global__ void k_convert(const float* __restrict__ W) {
    size_t i = ((size_t)blockIdx.x * blockDim.x + threadIdx.x) * 4;
    float4 v = *(const float4*)(W + i);
    g_wout[i + 0] = __float2bfloat16(v.x);
    g_wout[i + 1] = __float2bfloat16(v.y);
    g_wout[i + 2] = __float2bfloat16(v.z);
    g_wout[i + 3] = __float2bfloat16(v.w);
}

// permuted gate weights: tile j, row r (0..127) -> gate q=r>>5, hidden j*32+(r&31)
__global__ void k_convw(const float* __restrict__ W_ih, const float* __restrict__ W_hh) {
    size_t i4 = ((size_t)blockIdx.x * blockDim.x + threadIdx.x) * 4;
    int kk = (int)(i4 % KK);
    int rr = (int)(i4 / KK);          // j*128 + r
    int j = rr >> 7, r = rr & 127;
    int srcrow = (r >> 5) * HH + j * 32 + (r & 31);
    float4 v;
    if (kk < EE) v = *(const float4*)&W_ih[(size_t)srcrow * EE + kk];
    else         v = *(const float4*)&W_hh[(size_t)srcrow * HH + (kk - EE)];
    g_wperm[i4 + 0] = __float2bfloat16(v.x);
    g_wperm[i4 + 1] = __float2bfloat16(v.y);
    g_wperm[i4 + 2] = __float2bfloat16(v.z);
    g_wperm[i4 + 3] = __float2bfloat16(v.w);
}

__global__ void k_convb(const float* __restrict__ b_ih, const float* __restrict__ b_hh) {
    int id = blockIdx.x * blockDim.x + threadIdx.x;   // 0..4095
    int j = id >> 7, r = id & 127;
    int srcrow = (r >> 5) * HH + j * 32 + (r & 31);
    g_biasp[id] = b_ih[srcrow] + b_hh[srcrow];
}

// ---------------- init ----------------
__global__ void k_init(const float* __restrict__ h0, const float* __restrict__ c0) {
    int i = blockIdx.x * blockDim.x + threadIdx.x;
    if (i < HH * BB) {
        int b = i / HH, k = i % HH;
        g_h[k * BB + b] = h0[i];
        g_c[k * BB + b] = c0[i];
        g_hb[i] = __float2bfloat16(h0[i]);   // [b][k]
    }
    if (i == 0) g_loss = 0.f;
}

// ---------------- fused gates GEMM (bf16 HMMA) + LSTM pointwise ----------------
// 32 CTAs x 256 thr (8 warps). Tile j: gate rows for hidden units j*32..j*32+31
// (tile rows 0-31 = i, 32-63 = f, 64-95 = g, 96-127 = o). K=1536 in 24 chunks of 64.
// B tile: E-chunks gathered from emb (relu+cvt), H-chunks from g_hb.
__global__ void k_gateslstm(const int* __restrict__ indices, const float* __restrict__ emb,
                            int t) {
    __shared__ alignas(1024) char sbuf[16384 + 4096];
    const int tid = threadIdx.x;
    const int w = tid >> 5, lane = tid & 31;
    const int j = blockIdx.x;
    const uint32_t sbA = su32(sbuf);
    const uint32_t sbB = sbA + 16384u;

    const char* wbase = (const char*)(g_wperm + (size_t)j * 128 * KK);
    const int arow[4] = { (tid + 0) >> 3, (tid + 256) >> 3, (tid + 512) >> 3, (tid + 768) >> 3 };
    const int ac = tid & 7;
    const int brow = tid >> 3, bc = tid & 7;
    const int myidx = indices[t * BB + brow];

    float c[16];
    #pragma unroll
    for (int i = 0; i < 16; i++) c[i] = 0.f;

    float4 ra[4];
    uint4 rb;
    // prefetch chunk 0 (E part)
    #pragma unroll
    for (int i = 0; i < 4; i++)
        ra[i] = *(const float4*)(wbase + ((size_t)arow[i] * KK + ac * 8) * 2);
    {
        const float* e = emb + (size_t)myidx * EE + bc * 8;
        float4 v0 = *(const float4*)e, v1 = *(const float4*)(e + 4);
        rb.x = pack2(fmaxf(v0.x, 0.f), fmaxf(v0.y, 0.f));
        rb.y = pack2(fmaxf(v0.z, 0.f), fmaxf(v0.w, 0.f));
        rb.z = pack2(fmaxf(v1.x, 0.f), fmaxf(v1.y, 0.f));
        rb.w = pack2(fmaxf(v1.z, 0.f), fmaxf(v1.w, 0.f));
    }

    const int lr = lane & 15, lcs = (lane >> 4) << 3;
    const int bn = (lane & 7) + ((lane >> 4) << 3);
    const int bko = ((lane >> 3) & 1) << 3;

    for (int ch = 0; ch < 24; ch++) {
        __syncthreads();
        #pragma unroll
        for (int i = 0; i < 4; i++)
            *(float4*)(sbuf + SWZ(arow[i] * 128 + ac * 16)) = ra[i];
        *(uint4*)(sbuf + 16384 + SWZ(brow * 128 + bc * 16)) = rb;
        __syncthreads();

        if (ch < 23) {
            int ko = (ch + 1) * 64;
            #pragma unroll
            for (int i = 0; i < 4; i++)
                ra[i] = *(const float4*)(wbase + ((size_t)arow[i] * KK + ko + ac * 8) * 2);
            if (ko < EE) {
                const float* e = emb + (size_t)myidx * EE + ko + bc * 8;
                float4 v0 = *(const float4*)e, v1 = *(const float4*)(e + 4);
                rb.x = pack2(fmaxf(v0.x, 0.f), fmaxf(v0.y, 0.f));
                rb.y = pack2(fmaxf(v0.z, 0.f), fmaxf(v0.w, 0.f));
                rb.z = pack2(fmaxf(v1.x, 0.f), fmaxf(v1.y, 0.f));
                rb.w = pack2(fmaxf(v1.z, 0.f), fmaxf(v1.w, 0.f));
            } else {
                rb = *(const uint4*)((const char*)g_hb + ((size_t)brow * HH + ko - EE + bc * 8) * 2);
            }
        }

        #pragma unroll
        for (int s = 0; s < 4; s++) {
            uint32_t a[4], b01[4], b23[4];
            ldm_x4(a,   sbA + SWZ((w * 16 + lr) * 128 + (s * 16 + lcs) * 2));
            ldm_x4(b01, sbB + SWZ(bn * 128 + (s * 16 + bko) * 2));
            ldm_x4(b23, sbB + SWZ((bn + 16) * 128 + (s * 16 + bko) * 2));
            mma16816(c + 0,  a, b01 + 0);
            mma16816(c + 4,  a, b01 + 2);
            mma16816(c + 8,  a, b23 + 0);
            mma16816(c + 12, a, b23 + 2);
        }
    }
    __syncthreads();

    // epilogue 1: gates + bias -> smem [128][33]
    float* sl = (float*)sbuf;
    {
        int r0 = w * 16 + (lane >> 2);
        float bias0 = g_biasp[j * 128 + r0];
        float bias1 = g_biasp[j * 128 + r0 + 8];
        #pragma unroll
        for (int g = 0; g < 4; g++) {
            int col = g * 8 + 2 * (lane & 3);
            sl[r0 * 33 + col]           = c[g * 4 + 0] + bias0;
            sl[r0 * 33 + col + 1]       = c[g * 4 + 1] + bias0;
            sl[(r0 + 8) * 33 + col]     = c[g * 4 + 2] + bias1;
            sl[(r0 + 8) * 33 + col + 1] = c[g * 4 + 3] + bias1;
        }
    }
    __syncthreads();

    // epilogue 2: LSTM update for hidden units j*32..j*32+31, all batches
    {
        int hu = tid >> 3;              // 0..31
        int b0 = (tid & 7) * 4;         // 4 batches
        int k = j * 32 + hu;
        #pragma unroll
        for (int q = 0; q < 4; q++) {
            int b = b0 + q;
            float ig = sl[hu * 33 + b];
            float fg = sl[(32 + hu) * 33 + b];
            float gg = sl[(64 + hu) * 33 + b];
            float og = sl[(96 + hu) * 33 + b];
            float si = 1.f / (1.f + expf(-ig));
            float sf = 1.f / (1.f + expf(-fg));
            float so = 1.f / (1.f + expf(-og));
            float cn = sf * g_c[k * BB + b] + si * tanhf(gg);
            g_c[k * BB + b] = cn;
            float h = so * tanhf(cn);
            g_h[k * BB + b] = h;
            g_hb[b * HH + k] = __float2bfloat16(h);
        }
    }
}

// ---------------- logits via mma.sync bf16 HMMA ----------------
__global__ void k_logits_hmma(const float* __restrict__ b_out) {
    __shared__ alignas(1024) char sbuf[16384 + 4096];
    __shared__ float redM[4][32], redS[4][32];

    const int t = threadIdx.x;
    const int w = t >> 5, lane = t & 31;
    const int v0 = blockIdx.x * 128;
    const uint32_t sbA = su32(sbuf);
    const uint32_t sbB = sbA + 16384u;

    const char* wbase = (const char*)(g_wout + (size_t)v0 * HH);
    const char* hbase = (const char*)g_hb;

    const int arow[4] = { (t + 0) >> 3, (t + 256) >> 3, (t + 512) >> 3, (t + 768) >> 3 };
    const int ac = t & 7;
    const int brow = t >> 3, bc = t & 7;

    float c[16];
    #pragma unroll
    for (int i = 0; i < 16; i++) c[i] = 0.f;

    float4 ra[4], rb;
    #pragma unroll
    for (int i = 0; i < 4; i++)
        ra[i] = *(const float4*)(wbase + ((size_t)arow[i] * HH + ac * 8) * 2);
    rb = *(const float4*)(hbase + ((size_t)brow * HH + bc * 8) * 2);

    const int lr = lane & 15, lcs = (lane >> 4) << 3;
    const int bn = (lane & 7) + ((lane >> 4) << 3);
    const int bko = ((lane >> 3) & 1) << 3;

    for (int ch = 0; ch < 16; ch++) {
        __syncthreads();
        #pragma unroll
        for (int i = 0; i < 4; i++)
            *(float4*)(sbuf + SWZ(arow[i] * 128 + ac * 16)) = ra[i];
        *(float4*)(sbuf + 16384 + SWZ(brow * 128 + bc * 16)) = rb;
        __syncthreads();

        if (ch < 15) {
            int ko = (ch + 1) * 64;
            #pragma unroll
            for (int i = 0; i < 4; i++)
                ra[i] = *(const float4*)(wbase + ((size_t)arow[i] * HH + ko + ac * 8) * 2);
            rb = *(const float4*)(hbase + ((size_t)brow * HH + ko + bc * 8) * 2);
        }

        #pragma unroll
        for (int s = 0; s < 4; s++) {
            uint32_t a[4], b01[4], b23[4];
            ldm_x4(a,   sbA + SWZ((w * 16 + lr) * 128 + (s * 16 + lcs) * 2));
            ldm_x4(b01, sbB + SWZ(bn * 128 + (s * 16 + bko) * 2));
            ldm_x4(b23, sbB + SWZ((bn + 16) * 128 + (s * 16 + bko) * 2));
            mma16816(c + 0,  a, b01 + 0);
            mma16816(c + 4,  a, b01 + 2);
            mma16816(c + 8,  a, b23 + 0);
            mma16816(c + 12, a, b23 + 2);
        }
    }
    __syncthreads();

    float* sl = (float*)sbuf;
    {
        int r0 = w * 16 + (lane >> 2);
        float bias0 = b_out[v0 + r0];
        float bias1 = b_out[v0 + r0 + 8];
        #pragma unroll
        for (int g = 0; g < 4; g++) {
            int col = g * 8 + 2 * (lane & 3);
            sl[r0 * 33 + col]           = c[g * 4 + 0] + bias0;
            sl[r0 * 33 + col + 1]       = c[g * 4 + 1] + bias0;
            sl[(r0 + 8) * 33 + col]     = c[g * 4 + 2] + bias1;
            sl[(r0 + 8) * 33 + col + 1] = c[g * 4 + 3] + bias1;
        }
    }
    __syncthreads();

    if (t < 128) {
        int q = t >> 5, b = t & 31;
        float M = -1e30f, S = 0.f;
        #pragma unroll
        for (int r = 0; r < 32; r++) {
            float l = sl[(q * 32 + r) * 33 + b];
            if (l > M) { S = S * expf(M - l) + 1.f; M = l; }
            else       { S += expf(l - M); }
        }
        redM[q][b] = M; redS[q][b] = S;
    }
    __syncthreads();
    if (t < 32) {
        float M = -1e30f, S = 0.f;
        #pragma unroll
        for (int q = 0; q < 4; q++) {
            float m2 = redM[q][t], s2 = redS[q][t];
            if (m2 > M) { S = S * expf(M - m2) + s2; M = m2; }
            else        { S += s2 * expf(m2 - M); }
        }
        g_part[blockIdx.x * BB + t] = make_float2(M, S);
    }
}

// ---------------- merge chunks, target logit, accumulate loss ----------------
__global__ void k_merge(const int* __restrict__ indices, const float* __restrict__ W_out,
                        const float* __restrict__ b_out, int t) {
    __shared__ float nll[32];
    int tid = threadIdx.x;
    int w = tid >> 5;
    int l = tid & 31;
    float M = -1e30f;
    for (int c = l; c < NCHUNK; c += 32) M = fmaxf(M, g_part[c * BB + w].x);
    #pragma unroll
    for (int o = 16; o; o >>= 1) M = fmaxf(M, __shfl_xor_sync(0xFFFFFFFFu, M, o));
    float S = 0.f;
    for (int c = l; c < NCHUNK; c += 32) {
        float2 p = g_part[c * BB + w];
        S += p.y * expf(p.x - M);
    }
    #pragma unroll
    for (int o = 16; o; o >>= 1) S += __shfl_xor_sync(0xFFFFFFFFu, S, o);
    int tgt = indices[(t + 1) * BB + w];
    float z = 0.f;
    for (int e = l; e < HH; e += 32) z += g_h[e * BB + w] * W_out[tgt * HH + e];
    #pragma unroll
    for (int o = 16; o; o >>= 1) z += __shfl_xor_sync(0xFFFFFFFFu, z, o);
    if (l == 0) nll[w] = (tgt != 0) ? (logf(S) + M - (z + b_out[tgt])) : 0.f;
    __syncthreads();
    if (tid == 0) {
        float acc = g_loss;
        #pragma unroll
        for (int b = 0; b < 32; b++) acc += nll[b];
        g_loss = acc;
    }
}

__global__ void k_out(float* out, int n) {
    int i = blockIdx.x * blockDim.x + threadIdx.x;
    if (i < n) out[i] = (i == 0) ? g_loss : 0.f;
}

// ---------------- launch ----------------
extern "C" void kernel_launch(void* const* d_in, const int* in_sizes, int n_in,
                              void* d_out, int out_size) {
    const int*   indices = (const int*)d_in[0];
    const float* emb     = (const float*)d_in[1];
    const float* W_ih    = (const float*)d_in[2];
    const float* W_hh    = (const float*)d_in[3];
    const float* b_ih    = (const float*)d_in[4];
    const float* b_hh    = (const float*)d_in[5];
    const float* W_out   = (const float*)d_in[6];
    const float* b_out   = (const float*)d_in[7];
    const float* h0      = (const float*)d_in[8];
    const float* c0      = (const float*)d_in[9];

    k_convert<<<(VV * HH / 4) / 256, 256>>>(W_out);
    k_convw<<<(GG * KK / 4) / 256, 256>>>(W_ih, W_hh);
    k_convb<<<GG / 256, 256>>>(b_ih, b_hh);
    k_init<<<(HH * BB + 255) / 256, 256>>>(h0, c0);
    for (int t = 0; t < TT - 1; t++) {
        k_gateslstm<<<32, 256>>>(indices, emb, t);
        k_logits_hmma<<<NCHUNK, 256>>>(b_out);
        k_merge<<<1, 1024>>>(indices, W_out, b_out, t);
    }
    k_out<<<(out_size + 255) / 256, 256>>>((float*)d_out, out_size);
}

// round 7
// speedup vs baseline: 5.4307x; 1.7308x over previous
#include <cuda_runtime.h>
#include <cuda_bf16.h>
#include <stdint.h>
#include <stddef.h>
#include <math.h>

#define TT 128
#define BB 32
#define VV 32000
#define EE 512
#define HH 1024
#define KK 1536          // E + H
#define GG 4096          // 4H
#define NCHUNK 250       // logits chunks of 128 vocab rows
#define STAGE 20480      // logits pipeline stage bytes (A 16K + B 4K)

// ---------------- scratch (no allocations allowed) ----------------
__device__ __align__(16) float g_h3[3][HH * BB];        // h fp32, [k][b], triple-buffered
__device__ __align__(16) __nv_bfloat16 g_hb3[3][BB * HH]; // h bf16, [b][k], triple-buffered
__device__ __align__(16) float g_c[HH * BB];            // c[k][b]
__device__ __align__(16) __nv_bfloat16 g_wout[(size_t)VV * HH]; // W_out bf16 (64MB)
__device__ __align__(16) __nv_bfloat16 g_wperm[(size_t)GG * KK]; // permuted W_ih|W_hh bf16
__device__ __align__(16) float g_biasp[GG];             // permuted b_ih+b_hh
__device__ float2 g_part[2][NCHUNK * BB];               // (max,sumexp), double-buffered
__device__ float g_loss;

// ---------------- helpers ----------------
__device__ __forceinline__ uint32_t su32(const void* p) {
    uint32_t a;
    asm("{ .reg .u64 t; cvta.to.shared.u64 t, %1; cvt.u32.u64 %0, t; }" : "=r"(a) : "l"(p));
    return a;
}
#define SWZ(o) ((o) ^ (((o) >> 3) & 0x70))

__device__ __forceinline__ void ldm_x4(uint32_t* r, uint32_t addr) {
    asm volatile("ldmatrix.sync.aligned.m8n8.x4.shared.b16 {%0,%1,%2,%3}, [%4];"
                 : "=r"(r[0]), "=r"(r[1]), "=r"(r[2]), "=r"(r[3]) : "r"(addr));
}
__device__ __forceinline__ void mma16816(float* c, const uint32_t* a, const uint32_t* b) {
    asm volatile("mma.sync.aligned.m16n8k16.row.col.f32.bf16.bf16.f32 "
                 "{%0,%1,%2,%3}, {%4,%5,%6,%7}, {%8,%9}, {%0,%1,%2,%3};"
                 : "+f"(c[0]), "+f"(c[1]), "+f"(c[2]), "+f"(c[3])
                 : "r"(a[0]), "r"(a[1]), "r"(a[2]), "r"(a[3]), "r"(b[0]), "r"(b[1]));
}
__device__ __forceinline__ uint32_t pack2(float a, float b) {
    __nv_bfloat162 p = __floats2bfloat162_rn(a, b);
    return *reinterpret_cast<uint32_t*>(&p);
}
__device__ __forceinline__ void cpa16(uint32_t dst, const void* src) {
    asm volatile("cp.async.cg.shared.global [%0], [%1], 16;" :: "r"(dst), "l"(src) : "memory");
}
#define CPA_COMMIT() asm volatile("cp.async.commit_group;" ::: "memory")
#define CPA_WAIT1()  asm volatile("cp.async.wait_group 1;" ::: "memory")
#define CPA_WAIT0()  asm volatile("cp.async.wait_group 0;" ::: "memory")

// ---------------- one-time conversions ----------------
__global__ void k_convert(const float* __restrict__ W) {
    size_t i = ((size_t)blockIdx.x * blockDim.x + threadIdx.x) * 4;
    float4 v = *(const float4*)(W + i);
    g_wout[i + 0] = __float2bfloat16(v.x);
    g_wout[i + 1] = __float2bfloat16(v.y);
    g_wout[i + 2] = __float2bfloat16(v.z);
    g_wout[i + 3] = __float2bfloat16(v.w);
}
__global__ void k_convw(const float* __restrict__ W_ih, const float* __restrict__ W_hh) {
    size_t i4 = ((size_t)blockIdx.x * blockDim.x + threadIdx.x) * 4;
    int kk = (int)(i4 % KK);
    int rr = (int)(i4 / KK);
    int j = rr >> 7, r = rr & 127;
    int srcrow = (r >> 5) * HH + j * 32 + (r & 31);
    float4 v;
    if (kk < EE) v = *(const float4*)&W_ih[(size_t)srcrow * EE + kk];
    else         v = *(const float4*)&W_hh[(size_t)srcrow * HH + (kk - EE)];
    g_wperm[i4 + 0] = __float2bfloat16(v.x);
    g_wperm[i4 + 1] = __float2bfloat16(v.y);
    g_wperm[i4 + 2] = __float2bfloat16(v.z);
    g_wperm[i4 + 3] = __float2bfloat16(v.w);
}
__global__ void k_convb(const float* __restrict__ b_ih, const float* __restrict__ b_hh) {
    int id = blockIdx.x * blockDim.x + threadIdx.x;
    int j = id >> 7, r = id & 127;
    int srcrow = (r >> 5) * HH + j * 32 + (r & 31);
    g_biasp[id] = b_ih[srcrow] + b_hh[srcrow];
}
__global__ void k_init(const float* __restrict__ h0, const float* __restrict__ c0) {
    int i = blockIdx.x * blockDim.x + threadIdx.x;
    if (i < HH * BB) {
        int b = i / HH, k = i % HH;
        g_h3[0][k * BB + b] = h0[i];
        g_c[k * BB + b] = c0[i];
        g_hb3[0][i] = __float2bfloat16(h0[i]);
    }
    if (i == 0) g_loss = 0.f;
}

// ---------------- gates GEMM + LSTM device function ----------------
// Computes h(s+1): reads h buf s%3, c; writes buf (s+1)%3, c. CTA handles tile jj.
__device__ void gates_dev(const int* __restrict__ indices, const float* __restrict__ emb,
                          int s, int jj, char* sbuf) {
    const int tid = threadIdx.x;
    const int w = tid >> 5, lane = tid & 31;
    const uint32_t sbA = su32(sbuf);
    const uint32_t sbB = sbA + 16384u;
    const __nv_bfloat16* hbin = g_hb3[s % 3];
    const int out = (s + 1) % 3;

    const char* wbase = (const char*)(g_wperm + (size_t)jj * 128 * KK);
    const int arow[4] = { (tid + 0) >> 3, (tid + 256) >> 3, (tid + 512) >> 3, (tid + 768) >> 3 };
    const int ac = tid & 7;
    const int brow = tid >> 3, bc = tid & 7;
    const int myidx = indices[s * BB + brow];

    float c[16];
    #pragma unroll
    for (int i = 0; i < 16; i++) c[i] = 0.f;

    float4 ra[4];
    uint4 rb;
    #pragma unroll
    for (int i = 0; i < 4; i++)
        ra[i] = *(const float4*)(wbase + ((size_t)arow[i] * KK + ac * 8) * 2);
    {
        const float* e = emb + (size_t)myidx * EE + bc * 8;
        float4 v0 = *(const float4*)e, v1 = *(const float4*)(e + 4);
        rb.x = pack2(fmaxf(v0.x, 0.f), fmaxf(v0.y, 0.f));
        rb.y = pack2(fmaxf(v0.z, 0.f), fmaxf(v0.w, 0.f));
        rb.z = pack2(fmaxf(v1.x, 0.f), fmaxf(v1.y, 0.f));
        rb.w = pack2(fmaxf(v1.z, 0.f), fmaxf(v1.w, 0.f));
    }

    const int lr = lane & 15, lcs = (lane >> 4) << 3;
    const int bn = (lane & 7) + ((lane >> 4) << 3);
    const int bko = ((lane >> 3) & 1) << 3;

    for (int ch = 0; ch < 24; ch++) {
        __syncthreads();
        #pragma unroll
        for (int i = 0; i < 4; i++)
            *(float4*)(sbuf + SWZ(arow[i] * 128 + ac * 16)) = ra[i];
        *(uint4*)(sbuf + 16384 + SWZ(brow * 128 + bc * 16)) = rb;
        __syncthreads();

        if (ch < 23) {
            int ko = (ch + 1) * 64;
            #pragma unroll
            for (int i = 0; i < 4; i++)
                ra[i] = *(const float4*)(wbase + ((size_t)arow[i] * KK + ko + ac * 8) * 2);
            if (ko < EE) {
                const float* e = emb + (size_t)myidx * EE + ko + bc * 8;
                float4 v0 = *(const float4*)e, v1 = *(const float4*)(e + 4);
                rb.x = pack2(fmaxf(v0.x, 0.f), fmaxf(v0.y, 0.f));
                rb.y = pack2(fmaxf(v0.z, 0.f), fmaxf(v0.w, 0.f));
                rb.z = pack2(fmaxf(v1.x, 0.f), fmaxf(v1.y, 0.f));
                rb.w = pack2(fmaxf(v1.z, 0.f), fmaxf(v1.w, 0.f));
            } else {
                rb = *(const uint4*)((const char*)hbin + ((size_t)brow * HH + ko - EE + bc * 8) * 2);
            }
        }

        #pragma unroll
        for (int s4 = 0; s4 < 4; s4++) {
            uint32_t a[4], b01[4], b23[4];
            ldm_x4(a,   sbA + SWZ((w * 16 + lr) * 128 + (s4 * 16 + lcs) * 2));
            ldm_x4(b01, sbB + SWZ(bn * 128 + (s4 * 16 + bko) * 2));
            ldm_x4(b23, sbB + SWZ((bn + 16) * 128 + (s4 * 16 + bko) * 2));
            mma16816(c + 0,  a, b01 + 0);
            mma16816(c + 4,  a, b01 + 2);
            mma16816(c + 8,  a, b23 + 0);
            mma16816(c + 12, a, b23 + 2);
        }
    }
    __syncthreads();

    float* sl = (float*)sbuf;
    {
        int r0 = w * 16 + (lane >> 2);
        float bias0 = g_biasp[jj * 128 + r0];
        float bias1 = g_biasp[jj * 128 + r0 + 8];
        #pragma unroll
        for (int g = 0; g < 4; g++) {
            int col = g * 8 + 2 * (lane & 3);
            sl[r0 * 33 + col]           = c[g * 4 + 0] + bias0;
            sl[r0 * 33 + col + 1]       = c[g * 4 + 1] + bias0;
            sl[(r0 + 8) * 33 + col]     = c[g * 4 + 2] + bias1;
            sl[(r0 + 8) * 33 + col + 1] = c[g * 4 + 3] + bias1;
        }
    }
    __syncthreads();
    {
        int hu = tid >> 3;
        int b0 = (tid & 7) * 4;
        int k = jj * 32 + hu;
        #pragma unroll
        for (int q = 0; q < 4; q++) {
            int b = b0 + q;
            float ig = sl[hu * 33 + b];
            float fg = sl[(32 + hu) * 33 + b];
            float gg = sl[(64 + hu) * 33 + b];
            float og = sl[(96 + hu) * 33 + b];
            float si = 1.f / (1.f + expf(-ig));
            float sf = 1.f / (1.f + expf(-fg));
            float so = 1.f / (1.f + expf(-og));
            float cn = sf * g_c[k * BB + b] + si * tanhf(gg);
            g_c[k * BB + b] = cn;
            float h = so * tanhf(cn);
            g_h3[out][k * BB + b] = h;
            g_hb3[out][b * HH + k] = __float2bfloat16(h);
        }
    }
}

// ---------------- logits device function (3-stage cp.async) ----------------
// logits(t): reads h buf (t+1)%3, writes g_part[t&1]. CTA = vocab chunk blockIdx.x.
__device__ void logits_dev(const float* __restrict__ b_out, int t, char* sbuf,
                           float (*redM)[32], float (*redS)[32]) {
    const int tid = threadIdx.x;
    const int w = tid >> 5, lane = tid & 31;
    const int v0 = blockIdx.x * 128;
    const uint32_t sb = su32(sbuf);

    const char* wbase = (const char*)(g_wout + (size_t)v0 * HH);
    const char* hbase = (const char*)g_hb3[(t + 1) % 3];

    const int arow[4] = { (tid + 0) >> 3, (tid + 256) >> 3, (tid + 512) >> 3, (tid + 768) >> 3 };
    const int ac = tid & 7;
    const int brow = tid >> 3, bc = tid & 7;

    // per-thread precomputed swizzled dst offsets (within a stage)
    uint32_t dA[4];
    #pragma unroll
    for (int i = 0; i < 4; i++) dA[i] = SWZ(arow[i] * 128 + ac * 16);
    const uint32_t dB = 16384u + SWZ(brow * 128 + bc * 16);

    #define ISSUE(st, ch) do { \
        uint32_t base = sb + (st) * STAGE; \
        _Pragma("unroll") \
        for (int i = 0; i < 4; i++) \
            cpa16(base + dA[i], wbase + ((size_t)arow[i] * HH + (ch) * 64 + ac * 8) * 2); \
        cpa16(base + dB, hbase + ((size_t)brow * HH + (ch) * 64 + bc * 8) * 2); \
        CPA_COMMIT(); \
    } while (0)

    ISSUE(0, 0);
    ISSUE(1, 1);

    float c[16];
    #pragma unroll
    for (int i = 0; i < 16; i++) c[i] = 0.f;

    const int lr = lane & 15, lcs = (lane >> 4) << 3;
    const int bn = (lane & 7) + ((lane >> 4) << 3);
    const int bko = ((lane >> 3) & 1) << 3;

    for (int ch = 0; ch < 16; ch++) {
        if (ch == 15) CPA_WAIT0(); else CPA_WAIT1();
        __syncthreads();
        if (ch < 14) ISSUE((ch + 2) % 3, ch + 2);

        uint32_t sA = sb + (ch % 3) * STAGE;
        uint32_t sB = sA + 16384u;
        #pragma unroll
        for (int s4 = 0; s4 < 4; s4++) {
            uint32_t a[4], b01[4], b23[4];
            ldm_x4(a,   sA + SWZ((w * 16 + lr) * 128 + (s4 * 16 + lcs) * 2));
            ldm_x4(b01, sB + SWZ(bn * 128 + (s4 * 16 + bko) * 2));
            ldm_x4(b23, sB + SWZ((bn + 16) * 128 + (s4 * 16 + bko) * 2));
            mma16816(c + 0,  a, b01 + 0);
            mma16816(c + 4,  a, b01 + 2);
            mma16816(c + 8,  a, b23 + 0);
            mma16816(c + 12, a, b23 + 2);
        }
    }
    #undef ISSUE
    __syncthreads();

    float* sl = (float*)sbuf;
    {
        int r0 = w * 16 + (lane >> 2);
        float bias0 = b_out[v0 + r0];
        float bias1 = b_out[v0 + r0 + 8];
        #pragma unroll
        for (int g = 0; g < 4; g++) {
            int col = g * 8 + 2 * (lane & 3);
            sl[r0 * 33 + col]           = c[g * 4 + 0] + bias0;
            sl[r0 * 33 + col + 1]       = c[g * 4 + 1] + bias0;
            sl[(r0 + 8) * 33 + col]     = c[g * 4 + 2] + bias1;
            sl[(r0 + 8) * 33 + col + 1] = c[g * 4 + 3] + bias1;
        }
    }
    __syncthreads();

    if (tid < 128) {
        int q = tid >> 5, b = tid & 31;
        float M = -1e30f, S = 0.f;
        #pragma unroll
        for (int r = 0; r < 32; r++) {
            float l = sl[(q * 32 + r) * 33 + b];
            if (l > M) { S = S * expf(M - l) + 1.f; M = l; }
            else       { S += expf(l - M); }
        }
        redM[q][b] = M; redS[q][b] = S;
    }
    __syncthreads();
    if (tid < 32) {
        float M = -1e30f, S = 0.f;
        #pragma unroll
        for (int q = 0; q < 4; q++) {
            float m2 = redM[q][tid], s2 = redS[q][tid];
            if (m2 > M) { S = S * expf(M - m2) + s2; M = m2; }
            else        { S += s2 * expf(m2 - M); }
        }
        g_part[t & 1][blockIdx.x * BB + tid] = make_float2(M, S);
    }
}

// ---------------- merge device function (256 threads) ----------------
// merge(tau): reads g_part[tau&1], h buf (tau+1)%3, target idx(tau+1).
__device__ void merge_dev(const int* __restrict__ indices, const float* __restrict__ W_out,
                          const float* __restrict__ b_out, int tau, float* nll) {
    const int tid = threadIdx.x;
    const int wid = tid >> 5, l = tid & 31;
    const float2* part = g_part[tau & 1];
    const float* hfp = g_h3[(tau + 1) % 3];

    for (int b = wid; b < 32; b += 8) {
        float M = -1e30f;
        for (int c = l; c < NCHUNK; c += 32) M = fmaxf(M, part[c * BB + b].x);
        #pragma unroll
        for (int o = 16; o; o >>= 1) M = fmaxf(M, __shfl_xor_sync(0xFFFFFFFFu, M, o));
        float S = 0.f;
        for (int c = l; c < NCHUNK; c += 32) {
            float2 p = part[c * BB + b];
            S += p.y * expf(p.x - M);
        }
        #pragma unroll
        for (int o = 16; o; o >>= 1) S += __shfl_xor_sync(0xFFFFFFFFu, S, o);
        int tgt = indices[(tau + 1) * BB + b];
        float z = 0.f;
        for (int e = l; e < HH; e += 32) z += hfp[e * BB + b] * W_out[(size_t)tgt * HH + e];
        #pragma unroll
        for (int o = 16; o; o >>= 1) z += __shfl_xor_sync(0xFFFFFFFFu, z, o);
        if (l == 0) nll[b] = (tgt != 0) ? (logf(S) + M - (z + b_out[tgt])) : 0.f;
    }
    __syncthreads();
    if (tid == 0) {
        float acc = g_loss;
        #pragma unroll
        for (int b = 0; b < 32; b++) acc += nll[b];
        g_loss = acc;
    }
}

// ---------------- fused per-step kernel ----------------
// CTAs 0-249: logits(t). CTAs 250-281: gates(t+1) if t<=125. CTA 282: merge(t-1) if t>=1.
__global__ void k_step(const int* __restrict__ indices, const float* __restrict__ emb,
                       const float* __restrict__ W_out, const float* __restrict__ b_out,
                       int t) {
    extern __shared__ char sbuf[];
    __shared__ float redM[4][32], redS[4][32];
    __shared__ float nll[32];
    int bid = blockIdx.x;
    if (bid < NCHUNK) {
        logits_dev(b_out, t, sbuf, redM, redS);
    } else if (bid < NCHUNK + 32) {
        if (t <= TT - 3) gates_dev(indices, emb, t + 1, bid - NCHUNK, sbuf);
    } else {
        if (t >= 1) merge_dev(indices, W_out, b_out, t - 1, nll);
    }
}

__global__ void k_gates0(const int* __restrict__ indices, const float* __restrict__ emb) {
    extern __shared__ char sbuf[];
    gates_dev(indices, emb, 0, blockIdx.x, sbuf);
}

__global__ void k_merge_tail(const int* __restrict__ indices, const float* __restrict__ W_out,
                             const float* __restrict__ b_out) {
    __shared__ float nll[32];
    merge_dev(indices, W_out, b_out, TT - 2, nll);
}

__global__ void k_out(float* out, int n) {
    int i = blockIdx.x * blockDim.x + threadIdx.x;
    if (i < n) out[i] = (i == 0) ? g_loss : 0.f;
}

// ---------------- launch ----------------
extern "C" void kernel_launch(void* const* d_in, const int* in_sizes, int n_in,
                              void* d_out, int out_size) {
    const int*   indices = (const int*)d_in[0];
    const float* emb     = (const float*)d_in[1];
    const float* W_ih    = (const float*)d_in[2];
    const float* W_hh    = (const float*)d_in[3];
    const float* b_ih    = (const float*)d_in[4];
    const float* b_hh    = (const float*)d_in[5];
    const float* W_out   = (const float*)d_in[6];
    const float* b_out   = (const float*)d_in[7];
    const float* h0      = (const float*)d_in[8];
    const float* c0      = (const float*)d_in[9];

    cudaFuncSetAttribute(k_step, cudaFuncAttributeMaxDynamicSharedMemorySize, 3 * STAGE);

    k_convert<<<(VV * HH / 4) / 256, 256>>>(W_out);
    k_convw<<<(GG * KK / 4) / 256, 256>>>(W_ih, W_hh);
    k_convb<<<GG / 256, 256>>>(b_ih, b_hh);
    k_init<<<(HH * BB + 255) / 256, 256>>>(h0, c0);

    k_gates0<<<32, 256, STAGE>>>(indices, emb);
    for (int t = 0; t < TT - 1; t++)
        k_step<<<NCHUNK + 32 + 1, 256, 3 * STAGE>>>(indices, emb, W_out, b_out, t);
    k_merge_tail<<<1, 256>>>(indices, W_out, b_out);
    k_out<<<(out_size + 255) / 256, 256>>>((float*)d_out, out_size);
}